// round 2
// baseline (speedup 1.0000x reference)
#include <cuda_runtime.h>
#include <math_constants.h>

// Problem constants (fixed by the reference: B=4, S=2048, D_IN=D_OUT=1024)
constexpr int BATCH = 4;
constexpr int SEQ   = 2048;
constexpr int DIM   = 1024;
constexpr int MTOT  = BATCH * SEQ;   // 8192

// Scratch in __device__ globals (no allocation allowed in kernel_launch)
__device__ float g_Q[(size_t)MTOT * DIM];           // 32 MB
__device__ float g_K[(size_t)MTOT * DIM];           // 32 MB
__device__ float g_V[(size_t)MTOT * DIM];           // 32 MB
__device__ float g_S[(size_t)BATCH * SEQ * SEQ];    // 64 MB (scores -> attn probs)
__device__ float g_O[(size_t)MTOT * DIM];           // 32 MB (attn @ V)

// ---------------------------------------------------------------------------
// Tiled fp32 GEMM: C = alpha * A @ op(B)  (+ bias broadcast over rows)
//   A: M x K row-major
//   B: K x N row-major (TRANS_B=false)  or  N x K row-major (TRANS_B=true)
//   C: M x N row-major
// 128x128 block tile, BK=16, 256 threads, 8x8 per-thread microkernel.
// All dims must be multiples of the tile sizes (true for this problem).
// blockIdx.z selects batch via the given element strides.
// ---------------------------------------------------------------------------
#define BM 128
#define BN 128
#define BKK 16
#define TM 8
#define TN 8

template<bool TRANS_B, bool ADD_BIAS>
__global__ __launch_bounds__(256, 2)
void sgemm_kernel(const float* __restrict__ A,
                  const float* __restrict__ B,
                  const float* __restrict__ bias,
                  float* __restrict__ C,
                  int M, int N, int K, float alpha,
                  long long strideA, long long strideB, long long strideC)
{
    A += (long long)blockIdx.z * strideA;
    B += (long long)blockIdx.z * strideB;
    C += (long long)blockIdx.z * strideC;

    __shared__ float As[BKK][BM];
    __shared__ float Bs[BKK][BN];

    const int tid = threadIdx.x;
    const int rowBase = blockIdx.y * BM;
    const int colBase = blockIdx.x * BN;

    const int ty = tid >> 4;   // 0..15
    const int tx = tid & 15;   // 0..15

    float acc[TM][TN];
    #pragma unroll
    for (int i = 0; i < TM; i++)
        #pragma unroll
        for (int j = 0; j < TN; j++)
            acc[i][j] = 0.0f;

    for (int k0 = 0; k0 < K; k0 += BKK) {
        // ---- load A tile: 128 rows x 16 cols (row-major, lda = K) ----
        #pragma unroll
        for (int l = 0; l < 2; l++) {
            int idx = tid + l * 256;          // float4 index, 0..511
            int r   = idx >> 2;               // 0..127
            int c4  = (idx & 3) << 2;         // 0,4,8,12
            float4 v = *reinterpret_cast<const float4*>(
                A + (long long)(rowBase + r) * K + k0 + c4);
            As[c4 + 0][r] = v.x;
            As[c4 + 1][r] = v.y;
            As[c4 + 2][r] = v.z;
            As[c4 + 3][r] = v.w;
        }
        // ---- load B tile ----
        if (TRANS_B) {
            // B is N x K row-major; tile = 128 B-rows x 16 K-cols
            #pragma unroll
            for (int l = 0; l < 2; l++) {
                int idx = tid + l * 256;
                int r   = idx >> 2;
                int c4  = (idx & 3) << 2;
                float4 v = *reinterpret_cast<const float4*>(
                    B + (long long)(colBase + r) * K + k0 + c4);
                Bs[c4 + 0][r] = v.x;
                Bs[c4 + 1][r] = v.y;
                Bs[c4 + 2][r] = v.z;
                Bs[c4 + 3][r] = v.w;
            }
        } else {
            // B is K x N row-major; tile = 16 K-rows x 128 N-cols
            #pragma unroll
            for (int l = 0; l < 2; l++) {
                int idx = tid + l * 256;      // float4 index
                int r   = idx >> 5;           // 0..15
                int c   = (idx & 31) << 2;    // 0..124 step 4
                *reinterpret_cast<float4*>(&Bs[r][c]) =
                    *reinterpret_cast<const float4*>(
                        B + (long long)(k0 + r) * N + colBase + c);
            }
        }
        __syncthreads();

        // ---- 8x8 microkernel over BK ----
        #pragma unroll
        for (int k = 0; k < BKK; k++) {
            float ra[TM], rb[TN];
            *reinterpret_cast<float4*>(&ra[0]) = *reinterpret_cast<const float4*>(&As[k][ty * TM + 0]);
            *reinterpret_cast<float4*>(&ra[4]) = *reinterpret_cast<const float4*>(&As[k][ty * TM + 4]);
            *reinterpret_cast<float4*>(&rb[0]) = *reinterpret_cast<const float4*>(&Bs[k][tx * TN + 0]);
            *reinterpret_cast<float4*>(&rb[4]) = *reinterpret_cast<const float4*>(&Bs[k][tx * TN + 4]);
            #pragma unroll
            for (int i = 0; i < TM; i++)
                #pragma unroll
                for (int j = 0; j < TN; j++)
                    acc[i][j] = fmaf(ra[i], rb[j], acc[i][j]);
        }
        __syncthreads();
    }

    // ---- epilogue ----
    #pragma unroll
    for (int i = 0; i < TM; i++) {
        int row = rowBase + ty * TM + i;
        #pragma unroll
        for (int j = 0; j < TN; j += 4) {
            int col = colBase + tx * TN + j;
            float4 v;
            v.x = acc[i][j + 0] * alpha;
            v.y = acc[i][j + 1] * alpha;
            v.z = acc[i][j + 2] * alpha;
            v.w = acc[i][j + 3] * alpha;
            if (ADD_BIAS) {
                v.x += bias[col + 0];
                v.y += bias[col + 1];
                v.z += bias[col + 2];
                v.w += bias[col + 3];
            }
            *reinterpret_cast<float4*>(C + (long long)row * N + col) = v;
        }
    }
}

// ---------------------------------------------------------------------------
// Row-wise softmax over SEQ=2048 columns. One 256-thread block per row.
// ---------------------------------------------------------------------------
__global__ __launch_bounds__(256)
void softmax_rows_kernel(float* __restrict__ S)
{
    float* row = S + (long long)blockIdx.x * SEQ;
    const int tid = threadIdx.x;

    float v[8];
    float m = -CUDART_INF_F;
    #pragma unroll
    for (int i = 0; i < 8; i++) {
        v[i] = row[tid + i * 256];
        m = fmaxf(m, v[i]);
    }

    __shared__ float red[256];
    red[tid] = m;
    __syncthreads();
    #pragma unroll
    for (int s = 128; s > 0; s >>= 1) {
        if (tid < s) red[tid] = fmaxf(red[tid], red[tid + s]);
        __syncthreads();
    }
    m = red[0];
    __syncthreads();

    float sum = 0.0f;
    #pragma unroll
    for (int i = 0; i < 8; i++) {
        v[i] = __expf(v[i] - m);
        sum += v[i];
    }
    red[tid] = sum;
    __syncthreads();
    #pragma unroll
    for (int s = 128; s > 0; s >>= 1) {
        if (tid < s) red[tid] += red[tid + s];
        __syncthreads();
    }
    float inv = 1.0f / red[0];

    #pragma unroll
    for (int i = 0; i < 8; i++)
        row[tid + i * 256] = v[i] * inv;
}

// ---------------------------------------------------------------------------
// Launch
// Inputs (metadata order): inputs[B,S,D], Wq[D,D], Wk[D,D], Wv[D,D], Wo[D,D], bo[D]
// Output: float32 [B,S,D]
// ---------------------------------------------------------------------------
extern "C" void kernel_launch(void* const* d_in, const int* in_sizes, int n_in,
                              void* d_out, int out_size)
{
    const float* X  = (const float*)d_in[0];
    const float* Wq = (const float*)d_in[1];
    const float* Wk = (const float*)d_in[2];
    const float* Wv = (const float*)d_in[3];
    const float* Wo = (const float*)d_in[4];
    const float* bo = (const float*)d_in[5];
    float* out = (float*)d_out;

    float *Q, *K, *V, *S, *O;
    cudaGetSymbolAddress((void**)&Q, g_Q);
    cudaGetSymbolAddress((void**)&K, g_K);
    cudaGetSymbolAddress((void**)&V, g_V);
    cudaGetSymbolAddress((void**)&S, g_S);
    cudaGetSymbolAddress((void**)&O, g_O);

    dim3 block(256);
    const float scale = 1.0f / 32.0f;   // 1/sqrt(1024)

    // 1) QKV projections: [8192,1024] = X @ W  (NN, K=1024)
    {
        dim3 grid(DIM / BN, MTOT / BM, 1);
        sgemm_kernel<false, false><<<grid, block>>>(X, Wq, nullptr, Q,
            MTOT, DIM, DIM, 1.0f, 0, 0, 0);
        sgemm_kernel<false, false><<<grid, block>>>(X, Wk, nullptr, K,
            MTOT, DIM, DIM, 1.0f, 0, 0, 0);
        sgemm_kernel<false, false><<<grid, block>>>(X, Wv, nullptr, V,
            MTOT, DIM, DIM, 1.0f, 0, 0, 0);
    }

    // 2) scores: per batch, S_b = (Q_b @ K_b^T) * scale   (NT, M=N=2048, K=1024)
    {
        dim3 grid(SEQ / BN, SEQ / BM, BATCH);
        sgemm_kernel<true, false><<<grid, block>>>(Q, K, nullptr, S,
            SEQ, SEQ, DIM, scale,
            (long long)SEQ * DIM, (long long)SEQ * DIM, (long long)SEQ * SEQ);
    }

    // 3) row-wise softmax over all B*S rows
    softmax_rows_kernel<<<BATCH * SEQ, block>>>(S);

    // 4) O_b = P_b @ V_b   (NN, M=2048, N=1024, K=2048)
    {
        dim3 grid(DIM / BN, SEQ / BM, BATCH);
        sgemm_kernel<false, false><<<grid, block>>>(S, V, nullptr, O,
            SEQ, DIM, SEQ, 1.0f,
            (long long)SEQ * SEQ, (long long)SEQ * DIM, (long long)SEQ * DIM);
    }

    // 5) out = O @ Wo + bo   (NN, M=8192, N=1024, K=1024, bias)
    {
        dim3 grid(DIM / BN, MTOT / BM, 1);
        sgemm_kernel<false, true><<<grid, block>>>(O, Wo, bo, out,
            MTOT, DIM, DIM, 1.0f, 0, 0, 0);
    }
}

// round 4
// speedup vs baseline: 2.3162x; 2.3162x over previous
#include <cuda_runtime.h>
#include <cuda_bf16.h>
#include <cstdint>
#include <math_constants.h>

constexpr int BATCH = 4, SEQ = 2048, DIM = 1024, MTOT = BATCH * SEQ;

// ---- scratch (device globals; 16B-aligned for cp.async/float4) ----
__device__ __align__(16) __nv_bfloat16 g_Xhi [(size_t)MTOT * DIM];
__device__ __align__(16) __nv_bfloat16 g_Xlo [(size_t)MTOT * DIM];
__device__ __align__(16) __nv_bfloat16 g_Wth [4][(size_t)DIM * DIM];
__device__ __align__(16) __nv_bfloat16 g_Wtl [4][(size_t)DIM * DIM];
__device__ __align__(16) __nv_bfloat16 g_Qhi [(size_t)MTOT * DIM];
__device__ __align__(16) __nv_bfloat16 g_Qlo [(size_t)MTOT * DIM];
__device__ __align__(16) __nv_bfloat16 g_Khi [(size_t)MTOT * DIM];
__device__ __align__(16) __nv_bfloat16 g_Klo [(size_t)MTOT * DIM];
__device__ __align__(16) __nv_bfloat16 g_Vthi[(size_t)BATCH * DIM * SEQ];
__device__ __align__(16) __nv_bfloat16 g_Vtlo[(size_t)BATCH * DIM * SEQ];
__device__ __align__(16) float         g_S   [(size_t)BATCH * SEQ * SEQ];
__device__ __align__(16) __nv_bfloat16 g_Phi [(size_t)BATCH * SEQ * SEQ];
__device__ __align__(16) __nv_bfloat16 g_Plo [(size_t)BATCH * SEQ * SEQ];
__device__ __align__(16) __nv_bfloat16 g_Ohi [(size_t)MTOT * DIM];
__device__ __align__(16) __nv_bfloat16 g_Olo [(size_t)MTOT * DIM];

__device__ __forceinline__ uint32_t s2u(const void* p) {
    uint32_t a;
    asm("{ .reg .u64 t; cvta.to.shared.u64 t, %1; cvt.u32.u64 %0, t; }" : "=r"(a) : "l"(p));
    return a;
}
#define CPA16(dst, src) \
    asm volatile("cp.async.cg.shared.global [%0], [%1], 16;" :: "r"(dst), "l"(src) : "memory")
#define LDSM4(r, a) \
    asm volatile("ldmatrix.sync.aligned.m8n8.x4.shared.b16 {%0,%1,%2,%3}, [%4];" \
        : "=r"((r)[0]), "=r"((r)[1]), "=r"((r)[2]), "=r"((r)[3]) : "r"(a))
#define MMA16816(c, a, b0, b1) \
    asm volatile("mma.sync.aligned.m16n8k16.row.col.f32.bf16.bf16.f32 " \
        "{%0,%1,%2,%3}, {%4,%5,%6,%7}, {%8,%9}, {%0,%1,%2,%3};" \
        : "+f"((c)[0]), "+f"((c)[1]), "+f"((c)[2]), "+f"((c)[3]) \
        : "r"((a)[0]), "r"((a)[1]), "r"((a)[2]), "r"((a)[3]), "r"(b0), "r"(b1))

// ---- GEMM: D[m][n] = sum_k A[m][k]*B[n][k]; bf16x3 split via mma.sync ----
// CTA tile 128x128, 8 warps (2x4), warp tile 64x32, K-chunk 32, 3-stage cp.async.
// SMEM rows padded to 80B (conflict-free ldmatrix: bank unit (5r+c) mod 8).
constexpr int ROWB = 80;
constexpr int R_AH = 0, R_AL = 10240, R_BH = 20480, R_BL = 30720;
constexpr int STAGE_SZ = 40960;
constexpr int GEMM_SMEM = 3 * STAGE_SZ;      // 122880

// MODE 0: fp32 out (alpha, opt bias). MODE 1: bf16 hi/lo out. MODE 2: Vt hi/lo out.
template<int MODE, bool HASBIAS>
__global__ __launch_bounds__(256, 1)
void gemm_mma(const __nv_bfloat16* __restrict__ Ah, const __nv_bfloat16* __restrict__ Al,
              const __nv_bfloat16* __restrict__ Bh, const __nv_bfloat16* __restrict__ Bl,
              float* __restrict__ Cf,
              __nv_bfloat16* __restrict__ Ch, __nv_bfloat16* __restrict__ Cl,
              const float* __restrict__ bias,
              int Kd, int ldC, float alpha,
              long long aRowZ, long long bRowZ, long long cOffZ)
{
    extern __shared__ __align__(128) char smem[];
    const uint32_t sb = s2u(smem);
    const int tid = threadIdx.x, wid = tid >> 5, lane = tid & 31;
    const int wm = wid >> 2, wn = wid & 3;
    const int rowBase = blockIdx.y * 128, colBase = blockIdx.x * 128;
    const long long aRow0 = (long long)blockIdx.z * aRowZ + rowBase;
    const long long bRow0 = (long long)blockIdx.z * bRowZ + colBase;

    // ---- cp.async geometry: thread -> (row r=tid/4 in 0..63, granule c=tid&3) ----
    const int r = tid >> 2, cg = tid & 3;
    const long long rowStep = (long long)Kd * 2;           // bytes per gmem row
    const char* pAH = (const char*)Ah + (aRow0 + r) * rowStep + cg * 16;
    const char* pAL = (const char*)Al + (aRow0 + r) * rowStep + cg * 16;
    const char* pBH = (const char*)Bh + (bRow0 + r) * rowStep + cg * 16;
    const char* pBL = (const char*)Bl + (bRow0 + r) * rowStep + cg * 16;
    const uint32_t dRow = (uint32_t)(r * ROWB + cg * 16);
    const long long rowStep64 = 64 * rowStep;
    const int nCh = Kd >> 5;

    auto load_stage = [&](int c, int s) {
        const uint32_t d = sb + s * STAGE_SZ + dRow;
        const long long cb = (long long)c * 64;            // 32 bf16 = 64B per chunk
        #pragma unroll
        for (int i = 0; i < 2; i++) {
            CPA16(d + R_AH + i * 64 * ROWB, pAH + i * rowStep64 + cb);
            CPA16(d + R_AL + i * 64 * ROWB, pAL + i * rowStep64 + cb);
            CPA16(d + R_BH + i * 64 * ROWB, pBH + i * rowStep64 + cb);
            CPA16(d + R_BL + i * 64 * ROWB, pBL + i * rowStep64 + cb);
        }
        asm volatile("cp.async.commit_group;" ::: "memory");
    };

    // ---- ldmatrix lane bases ----
    const uint32_t aOff = (uint32_t)((wm * 64 + (lane & 7) + ((lane >> 3) & 1) * 8) * ROWB
                                     + ((lane >> 4) * 8) * 2);
    const uint32_t bOff = (uint32_t)((wn * 32 + (lane & 7) + ((lane >> 4) & 1) * 8) * ROWB
                                     + (((lane >> 3) & 1) * 8) * 2);

    float acc[4][4][4];
    #pragma unroll
    for (int i = 0; i < 4; i++)
        #pragma unroll
        for (int j = 0; j < 4; j++)
            #pragma unroll
            for (int q = 0; q < 4; q++) acc[i][j][q] = 0.0f;

    load_stage(0, 0);
    if (nCh > 1) load_stage(1, 1);

    for (int c = 0; c < nCh; c++) {
        const int s = c - (c / 3) * 3;
        if (c + 1 < nCh) asm volatile("cp.async.wait_group 1;" ::: "memory");
        else             asm volatile("cp.async.wait_group 0;" ::: "memory");
        __syncthreads();

        const uint32_t st = sb + s * STAGE_SZ;
        #pragma unroll
        for (int k16 = 0; k16 < 2; k16++) {
            uint32_t ah[4][4], al[4][4], bh[2][4], bl[2][4];
            #pragma unroll
            for (int mt = 0; mt < 4; mt++) {
                LDSM4(ah[mt], st + R_AH + aOff + mt * (16 * ROWB) + k16 * 32);
                LDSM4(al[mt], st + R_AL + aOff + mt * (16 * ROWB) + k16 * 32);
            }
            #pragma unroll
            for (int j = 0; j < 2; j++) {
                LDSM4(bh[j], st + R_BH + bOff + j * (16 * ROWB) + k16 * 32);
                LDSM4(bl[j], st + R_BL + bOff + j * (16 * ROWB) + k16 * 32);
            }
            #pragma unroll
            for (int mt = 0; mt < 4; mt++)
                #pragma unroll
                for (int nt = 0; nt < 4; nt++) {
                    const int jj = nt >> 1, hh = (nt & 1) * 2;
                    MMA16816(acc[mt][nt], ah[mt], bh[jj][hh], bh[jj][hh + 1]);
                    MMA16816(acc[mt][nt], ah[mt], bl[jj][hh], bl[jj][hh + 1]);
                    MMA16816(acc[mt][nt], al[mt], bh[jj][hh], bh[jj][hh + 1]);
                }
        }
        __syncthreads();
        if (c + 2 < nCh) load_stage(c + 2, (c + 2) - ((c + 2) / 3) * 3);
    }

    // ---- epilogue ----
    const int mBase = rowBase + wm * 64 + (lane >> 2);
    const int nBaseW = colBase + wn * 32 + (lane & 3) * 2;
    #pragma unroll
    for (int mt = 0; mt < 4; mt++) {
        #pragma unroll
        for (int nt = 0; nt < 4; nt++) {
            const int n = nBaseW + nt * 8;
            #pragma unroll
            for (int h = 0; h < 2; h++) {            // h=0: rows m, h=1: m+8
                const int m = mBase + mt * 16 + h * 8;
                float v0 = acc[mt][nt][h * 2 + 0] * alpha;
                float v1 = acc[mt][nt][h * 2 + 1] * alpha;
                if (MODE == 0) {
                    if (HASBIAS) { v0 += bias[n]; v1 += bias[n + 1]; }
                    float2 w; w.x = v0; w.y = v1;
                    *reinterpret_cast<float2*>(Cf + (long long)blockIdx.z * cOffZ
                        + (long long)m * ldC + n) = w;
                } else if (MODE == 1) {
                    __nv_bfloat16 h0 = __float2bfloat16(v0), h1 = __float2bfloat16(v1);
                    __nv_bfloat162 hp, lp;
                    hp.x = h0; hp.y = h1;
                    lp.x = __float2bfloat16(v0 - __bfloat162float(h0));
                    lp.y = __float2bfloat16(v1 - __bfloat162float(h1));
                    const long long base = (long long)blockIdx.z * cOffZ
                        + (long long)m * ldC + n;
                    *reinterpret_cast<__nv_bfloat162*>(Ch + base) = hp;
                    *reinterpret_cast<__nv_bfloat162*>(Cl + base) = lp;
                } else {   // MODE 2: V -> Vt[b][1024][2048]
                    const int b = rowBase >> 11;
                    const int ml = (rowBase & 2047) + wm * 64 + (lane >> 2) + mt * 16 + h * 8;
                    __nv_bfloat16 h0 = __float2bfloat16(v0), h1 = __float2bfloat16(v1);
                    const long long i0 = ((long long)(b * 1024 + n)) * 2048 + ml;
                    Ch[i0]        = h0;
                    Cl[i0]        = __float2bfloat16(v0 - __bfloat162float(h0));
                    Ch[i0 + 2048] = h1;
                    Cl[i0 + 2048] = __float2bfloat16(v1 - __bfloat162float(h1));
                }
            }
        }
    }
}

// ---- fp32 -> bf16 hi/lo split ----
__global__ __launch_bounds__(256)
void split_kernel(const float4* __restrict__ in, __nv_bfloat162* __restrict__ hi,
                  __nv_bfloat162* __restrict__ lo, int n4)
{
    int i = blockIdx.x * blockDim.x + threadIdx.x;
    if (i >= n4) return;
    float4 v = in[i];
    __nv_bfloat16 hx = __float2bfloat16(v.x), hy = __float2bfloat16(v.y);
    __nv_bfloat16 hz = __float2bfloat16(v.z), hw = __float2bfloat16(v.w);
    __nv_bfloat162 a, b, c, d;
    a.x = hx; a.y = hy; b.x = hz; b.y = hw;
    c.x = __float2bfloat16(v.x - __bfloat162float(hx));
    c.y = __float2bfloat16(v.y - __bfloat162float(hy));
    d.x = __float2bfloat16(v.z - __bfloat162float(hz));
    d.y = __float2bfloat16(v.w - __bfloat162float(hw));
    hi[(size_t)i*2] = a; hi[(size_t)i*2+1] = b;
    lo[(size_t)i*2] = c; lo[(size_t)i*2+1] = d;
}

// ---- W[1024][1024] -> Wt hi/lo (transpose + split) ----
__global__ __launch_bounds__(256)
void transpose_split_kernel(const float* __restrict__ W,
                            __nv_bfloat16* __restrict__ Th, __nv_bfloat16* __restrict__ Tl)
{
    __shared__ float t[32][33];
    int x = blockIdx.x * 32 + threadIdx.x;
    int y0 = blockIdx.y * 32;
    #pragma unroll
    for (int j = threadIdx.y; j < 32; j += 8)
        t[j][threadIdx.x] = W[(long long)(y0 + j) * DIM + x];
    __syncthreads();
    int xo = y0 + threadIdx.x;
    int yo = blockIdx.x * 32;
    #pragma unroll
    for (int j = threadIdx.y; j < 32; j += 8) {
        float v = t[threadIdx.x][j];
        __nv_bfloat16 h = __float2bfloat16(v);
        long long idx = (long long)(yo + j) * DIM + xo;
        Th[idx] = h;
        Tl[idx] = __float2bfloat16(v - __bfloat162float(h));
    }
}

// ---- softmax over 2048 cols + bf16 hi/lo split of P ----
__global__ __launch_bounds__(256)
void softmax_split_kernel(const float* __restrict__ S,
                          __nv_bfloat16* __restrict__ Ph, __nv_bfloat16* __restrict__ Pl)
{
    const float* row = S + (long long)blockIdx.x * SEQ;
    const int tid = threadIdx.x;
    float v[8], m = -CUDART_INF_F;
    #pragma unroll
    for (int i = 0; i < 8; i++) { v[i] = row[tid + i*256]; m = fmaxf(m, v[i]); }
    __shared__ float red[256];
    red[tid] = m; __syncthreads();
    #pragma unroll
    for (int s = 128; s > 0; s >>= 1) { if (tid < s) red[tid] = fmaxf(red[tid], red[tid+s]); __syncthreads(); }
    m = red[0]; __syncthreads();
    float sum = 0.f;
    #pragma unroll
    for (int i = 0; i < 8; i++) { v[i] = __expf(v[i] - m); sum += v[i]; }
    red[tid] = sum; __syncthreads();
    #pragma unroll
    for (int s = 128; s > 0; s >>= 1) { if (tid < s) red[tid] += red[tid+s]; __syncthreads(); }
    float inv = 1.0f / red[0];
    const long long base = (long long)blockIdx.x * SEQ;
    #pragma unroll
    for (int i = 0; i < 8; i++) {
        float p = v[i] * inv;
        __nv_bfloat16 h = __float2bfloat16(p);
        Ph[base + tid + i*256] = h;
        Pl[base + tid + i*256] = __float2bfloat16(p - __bfloat162float(h));
    }
}

// ---- launch ----
extern "C" void kernel_launch(void* const* d_in, const int* in_sizes, int n_in,
                              void* d_out, int out_size)
{
    const float* X  = (const float*)d_in[0];
    const float* Ws[4] = { (const float*)d_in[1], (const float*)d_in[2],
                           (const float*)d_in[3], (const float*)d_in[4] };
    const float* bo = (const float*)d_in[5];
    float* out = (float*)d_out;

    __nv_bfloat16 *Xhi, *Xlo, *Qhi, *Qlo, *Khi, *Klo, *Vthi, *Vtlo, *Phi, *Plo, *Ohi, *Olo;
    __nv_bfloat16 *Wth, *Wtl;
    float* Sc;
    cudaGetSymbolAddress((void**)&Xhi, g_Xhi);   cudaGetSymbolAddress((void**)&Xlo, g_Xlo);
    cudaGetSymbolAddress((void**)&Wth, g_Wth);   cudaGetSymbolAddress((void**)&Wtl, g_Wtl);
    cudaGetSymbolAddress((void**)&Qhi, g_Qhi);   cudaGetSymbolAddress((void**)&Qlo, g_Qlo);
    cudaGetSymbolAddress((void**)&Khi, g_Khi);   cudaGetSymbolAddress((void**)&Klo, g_Klo);
    cudaGetSymbolAddress((void**)&Vthi, g_Vthi); cudaGetSymbolAddress((void**)&Vtlo, g_Vtlo);
    cudaGetSymbolAddress((void**)&Sc, g_S);
    cudaGetSymbolAddress((void**)&Phi, g_Phi);   cudaGetSymbolAddress((void**)&Plo, g_Plo);
    cudaGetSymbolAddress((void**)&Ohi, g_Ohi);   cudaGetSymbolAddress((void**)&Olo, g_Olo);

    cudaFuncSetAttribute(gemm_mma<0,false>, cudaFuncAttributeMaxDynamicSharedMemorySize, GEMM_SMEM);
    cudaFuncSetAttribute(gemm_mma<0,true >, cudaFuncAttributeMaxDynamicSharedMemorySize, GEMM_SMEM);
    cudaFuncSetAttribute(gemm_mma<1,false>, cudaFuncAttributeMaxDynamicSharedMemorySize, GEMM_SMEM);
    cudaFuncSetAttribute(gemm_mma<2,false>, cudaFuncAttributeMaxDynamicSharedMemorySize, GEMM_SMEM);

    const size_t wsz = (size_t)DIM * DIM;
    dim3 blk(256);

    // conversions
    split_kernel<<<(MTOT*DIM/4 + 255)/256, blk>>>((const float4*)X,
        (__nv_bfloat162*)Xhi, (__nv_bfloat162*)Xlo, MTOT*DIM/4);
    {
        dim3 tb(32, 8), tg(DIM/32, DIM/32);
        for (int w = 0; w < 4; w++)
            transpose_split_kernel<<<tg, tb>>>(Ws[w], Wth + w*wsz, Wtl + w*wsz);
    }

    // Q,K,V projections: [8192,1024] = X @ W (B operands K-major = Wt)
    {
        dim3 g(DIM/128, MTOT/128, 1);
        gemm_mma<1,false><<<g, 256, GEMM_SMEM>>>(Xhi, Xlo, Wth + 0*wsz, Wtl + 0*wsz,
            nullptr, Qhi, Qlo, nullptr, DIM, DIM, 1.0f, 0, 0, 0);
        gemm_mma<1,false><<<g, 256, GEMM_SMEM>>>(Xhi, Xlo, Wth + 1*wsz, Wtl + 1*wsz,
            nullptr, Khi, Klo, nullptr, DIM, DIM, 1.0f, 0, 0, 0);
        gemm_mma<2,false><<<g, 256, GEMM_SMEM>>>(Xhi, Xlo, Wth + 2*wsz, Wtl + 2*wsz,
            nullptr, Vthi, Vtlo, nullptr, DIM, DIM, 1.0f, 0, 0, 0);
    }

    // scores = (Q @ K^T) / 32, fp32
    {
        dim3 g(SEQ/128, SEQ/128, BATCH);
        gemm_mma<0,false><<<g, 256, GEMM_SMEM>>>(Qhi, Qlo, Khi, Klo,
            Sc, nullptr, nullptr, nullptr, DIM, SEQ, 1.0f/32.0f,
            (long long)SEQ, (long long)SEQ, (long long)SEQ * SEQ);
    }

    // softmax + split -> P hi/lo
    softmax_split_kernel<<<BATCH*SEQ, blk>>>(Sc, Phi, Plo);

    // O = P @ V (B = Vt K-major, K=2048)
    {
        dim3 g(DIM/128, SEQ/128, BATCH);
        gemm_mma<1,false><<<g, 256, GEMM_SMEM>>>(Phi, Plo, Vthi, Vtlo,
            nullptr, Ohi, Olo, nullptr, SEQ, DIM, 1.0f,
            (long long)SEQ, (long long)DIM, (long long)SEQ * DIM);
    }

    // out = O @ Wo + bo
    {
        dim3 g(DIM/128, MTOT/128, 1);
        gemm_mma<0,true><<<g, 256, GEMM_SMEM>>>(Ohi, Olo, Wth + 3*wsz, Wtl + 3*wsz,
            out, nullptr, nullptr, bo, DIM, DIM, 1.0f, 0, 0, 0);
    }
}